// round 2
// baseline (speedup 1.0000x reference)
#include <cuda_runtime.h>
#include <math.h>

#define BB 32
#define TT 1024
#define FF 512
#define EE 512
#define HH 512
#define VV 5000
#define STEPS 64
#define KX (EE + FF)   // 1024

// ---------------- persistent device state ----------------
__device__ float g_xT[KX * BB];          // rnn input, transposed [K][B]
__device__ float g_hT[HH * BB];          // hidden,    [H][B]
__device__ float g_cT[HH * BB];          // cell,      [H][B]
__device__ float g_gatesT[4 * HH * BB];  // gates,     [4H][B]
__device__ float g_ctxT[FF * BB];        // context,   [F][B]
__device__ float g_hidT[512 * BB];       // mlp out,   [512][B]
__device__ int   g_tok[BB];

// ---------------- init: x0 = [emb[0], lf[:,0,:]], h=c=0 ----------------
__global__ void init_kernel(const float* __restrict__ emb, const float* __restrict__ lf)
{
    int idx = blockIdx.x * blockDim.x + threadIdx.x;
    if (idx >= KX * BB) return;
    int b = idx & 31, k = idx >> 5;
    if (k < EE) {
        g_xT[idx] = emb[k];
        g_hT[k * BB + b] = 0.f;
        g_cT[k * BB + b] = 0.f;
    } else {
        g_xT[idx] = lf[(size_t)b * TT * FF + (k - EE)];
    }
}

// ---------------- big GEMM: 8 j per block, 64 threads, 4 batches/thread ----
// out[j][b] = sum_k concat(p1,p2)[k][b] * Wrow(j)[k] + b1[j] (+b2[j])
__global__ void gemm4_kernel(const float* __restrict__ Wa, int strideA,
                             const float* __restrict__ Wb, int strideB,
                             int K1, int K2,
                             const float* __restrict__ p1, const float* __restrict__ p2,
                             const float* __restrict__ b1, const float* __restrict__ b2,
                             float* __restrict__ outT,
                             float* __restrict__ outRow, int rowStride,
                             int Jtot, int act)
{
    __shared__ float ws[8 * 1536];
    const int K = K1 + K2;
    const int j0 = blockIdx.x * 8;
    for (int idx = threadIdx.x; idx < 8 * K; idx += blockDim.x) {
        int r = idx / K, k = idx - r * K;
        int j = j0 + r;
        float v = 0.f;
        if (j < Jtot)
            v = (k < K1) ? Wa[(size_t)j * strideA + k]
                         : Wb[(size_t)j * strideB + (k - K1)];
        ws[r * K + k] = v;
    }
    __syncthreads();

    int tid = threadIdx.x;
    int bg = tid & 7;    // batch group: 4 consecutive b
    int jj = tid >> 3;   // 0..7
    int j = j0 + jj;
    const float* wr = ws + jj * K;
    float ax = 0.f, ay = 0.f, az = 0.f, aw = 0.f;
    const float4* p1v = (const float4*)p1;
    #pragma unroll 4
    for (int k = 0; k < K1; k++) {
        float w = wr[k];
        float4 x = p1v[k * 8 + bg];
        ax = fmaf(w, x.x, ax); ay = fmaf(w, x.y, ay);
        az = fmaf(w, x.z, az); aw = fmaf(w, x.w, aw);
    }
    if (K2 > 0) {
        const float4* p2v = (const float4*)p2;
        #pragma unroll 4
        for (int k = 0; k < K2; k++) {
            float w = wr[K1 + k];
            float4 x = p2v[k * 8 + bg];
            ax = fmaf(w, x.x, ax); ay = fmaf(w, x.y, ay);
            az = fmaf(w, x.z, az); aw = fmaf(w, x.w, aw);
        }
    }
    if (j < Jtot) {
        float bias = b1[j];
        if (b2) bias += b2[j];
        ax += bias; ay += bias; az += bias; aw += bias;
        if (act) {
            ax = fmaxf(ax, 0.f); ay = fmaxf(ay, 0.f);
            az = fmaxf(az, 0.f); aw = fmaxf(aw, 0.f);
        }
        if (outT) {
            ((float4*)outT)[j * 8 + bg] = make_float4(ax, ay, az, aw);
        }
        if (outRow) {
            int b0 = bg * 4;
            outRow[(size_t)(b0 + 0) * rowStride + j] = ax;
            outRow[(size_t)(b0 + 1) * rowStride + j] = ay;
            outRow[(size_t)(b0 + 2) * rowStride + j] = az;
            outRow[(size_t)(b0 + 3) * rowStride + j] = aw;
        }
    }
}

// ---------------- small GEMM for predict_hid (relu) ----------------
__global__ void gemm1_kernel(const float* __restrict__ Wa,
                             const float* __restrict__ p1, const float* __restrict__ p2,
                             const float* __restrict__ b1,
                             float* __restrict__ outT)
{
    __shared__ float ws[8 * 1024];
    int j0 = blockIdx.x * 8;
    for (int idx = threadIdx.x; idx < 8 * 1024; idx += blockDim.x) {
        int r = idx >> 10, k = idx & 1023;
        ws[idx] = Wa[(size_t)(j0 + r) * 1024 + k];
    }
    __syncthreads();
    int tid = threadIdx.x;
    int b = tid & 31, jj = tid >> 5;
    const float* wr = ws + jj * 1024;
    float acc = 0.f;
    #pragma unroll 4
    for (int k = 0; k < 512; k++) acc = fmaf(p1[k * 32 + b], wr[k], acc);
    #pragma unroll 4
    for (int k = 0; k < 512; k++) acc = fmaf(p2[k * 32 + b], wr[512 + k], acc);
    int j = j0 + jj;
    acc += b1[j];
    outT[j * 32 + b] = fmaxf(acc, 0.f);
}

// ---------------- LSTM gate nonlinearity ----------------
__global__ void lstm_gate_kernel()
{
    int idx = blockIdx.x * blockDim.x + threadIdx.x;
    if (idx >= HH * BB) return;
    float gi = g_gatesT[idx];
    float gf = g_gatesT[HH * BB + idx];
    float gg = g_gatesT[2 * HH * BB + idx];
    float go = g_gatesT[3 * HH * BB + idx];
    float si = 1.f / (1.f + __expf(-gi));
    float sf = 1.f / (1.f + __expf(-gf));
    float so = 1.f / (1.f + __expf(-go));
    float tg = tanhf(gg);
    float c = sf * g_cT[idx] + si * tg;
    g_cT[idx] = c;
    g_hT[idx] = so * tanhf(c);
}

// ---------------- attention: one block per (b, head) ----------------
__global__ void attention_kernel(const float* __restrict__ lf, float* __restrict__ attn_out)
{
    int b  = blockIdx.x & 31;
    int hh = blockIdx.x >> 5;
    __shared__ float e[TT];
    __shared__ float red[8];
    __shared__ float csh[256];
    int tid = threadIdx.x;
    int lane = tid & 31, wid = tid >> 5;

    // decoder-state slice for this head, 4 floats per lane
    float4 ds;
    int dbase = hh * 128 + lane * 4;
    ds.x = g_hT[(dbase + 0) * BB + b];
    ds.y = g_hT[(dbase + 1) * BB + b];
    ds.z = g_hT[(dbase + 2) * BB + b];
    ds.w = g_hT[(dbase + 3) * BB + b];

    // energy: one warp handles one t per iteration (coalesced 512B/t)
    const float4* lfb = (const float4*)(lf + (size_t)b * TT * FF + hh * 128);
    for (int t = wid; t < TT; t += 8) {
        float4 v = lfb[(size_t)t * (FF / 4) + lane];
        float p = ds.x * v.x + ds.y * v.y + ds.z * v.z + ds.w * v.w;
        #pragma unroll
        for (int off = 16; off; off >>= 1) p += __shfl_xor_sync(0xffffffffu, p, off);
        if (lane == 0) e[t] = p;
    }
    __syncthreads();

    // softmax max
    float m = -1e30f;
    for (int t = tid; t < TT; t += 256) m = fmaxf(m, e[t]);
    #pragma unroll
    for (int off = 16; off; off >>= 1) m = fmaxf(m, __shfl_xor_sync(0xffffffffu, m, off));
    if (lane == 0) red[wid] = m;
    __syncthreads();
    float mm = fmaxf(fmaxf(fmaxf(red[0], red[1]), fmaxf(red[2], red[3])),
                     fmaxf(fmaxf(red[4], red[5]), fmaxf(red[6], red[7])));
    __syncthreads();

    // exp + sum
    float ssum = 0.f;
    for (int t = tid; t < TT; t += 256) { float p = __expf(e[t] - mm); e[t] = p; ssum += p; }
    #pragma unroll
    for (int off = 16; off; off >>= 1) ssum += __shfl_xor_sync(0xffffffffu, ssum, off);
    if (lane == 0) red[wid] = ssum;
    __syncthreads();
    float tot = red[0] + red[1] + red[2] + red[3] + red[4] + red[5] + red[6] + red[7];
    float inv = 1.f / tot;

    for (int t = tid; t < TT; t += 256) {
        float p = e[t] * inv;
        e[t] = p;
        if (hh == 3) attn_out[(size_t)b * TT + t] = p;  // last head, per reference
    }
    __syncthreads();

    // context: 128 d-threads x 2 t-halves, coalesced over d
    int d = tid & 127, half = tid >> 7;
    const float* lfp = lf + (size_t)b * TT * FF + hh * 128 + d;
    float acc = 0.f;
    int t0 = half * 512;
    #pragma unroll 4
    for (int t = t0; t < t0 + 512; t++)
        acc = fmaf(e[t], lfp[(size_t)t * FF], acc);
    csh[tid] = acc;
    __syncthreads();
    if (tid < 128)
        g_ctxT[(hh * 128 + d) * BB + b] = csh[tid] + csh[tid + 128];
}

// ---------------- log_softmax (in place) + argmax ----------------
__global__ void lsm_argmax_kernel(float* __restrict__ logits)
{
    int b = blockIdx.x;
    float* row = logits + (size_t)b * VV;
    int tid = threadIdx.x;
    __shared__ float sv[256];
    __shared__ int   si[256];

    float m = -1e30f; int mi = VV;
    for (int j = tid; j < VV; j += 256) {
        float v = row[j];
        if (v > m) { m = v; mi = j; }   // strided increasing -> first max kept
    }
    sv[tid] = m; si[tid] = mi; __syncthreads();
    for (int st = 128; st; st >>= 1) {
        if (tid < st) {
            float v2 = sv[tid + st]; int i2 = si[tid + st];
            if (v2 > sv[tid] || (v2 == sv[tid] && i2 < si[tid])) { sv[tid] = v2; si[tid] = i2; }
        }
        __syncthreads();
    }
    float mm = sv[0];
    if (tid == 0) g_tok[b] = si[0];
    __syncthreads();

    float s = 0.f;
    for (int j = tid; j < VV; j += 256) s += __expf(row[j] - mm);
    sv[tid] = s; __syncthreads();
    for (int st = 128; st; st >>= 1) { if (tid < st) sv[tid] += sv[tid + st]; __syncthreads(); }
    float lse = mm + logf(sv[0]);
    for (int j = tid; j < VV; j += 256) row[j] -= lse;
}

// ---------------- next rnn input = [embedding[tok], context] ----------------
__global__ void next_input_kernel(const float* __restrict__ emb)
{
    int idx = blockIdx.x * blockDim.x + threadIdx.x;
    if (idx >= KX * BB) return;
    int b = idx & 31, k = idx >> 5;
    if (k < EE) g_xT[idx] = emb[(size_t)g_tok[b] * EE + k];
    else        g_xT[idx] = g_ctxT[(k - EE) * BB + b];
}

// ---------------- launcher ----------------
extern "C" void kernel_launch(void* const* d_in, const int* in_sizes, int n_in,
                              void* d_out, int out_size)
{
    const float* lf   = (const float*)d_in[0];
    const float* emb  = (const float*)d_in[1];
    const float* W_ih = (const float*)d_in[2];
    const float* W_hh = (const float*)d_in[3];
    const float* b_ih = (const float*)d_in[4];
    const float* b_hh = (const float*)d_in[5];
    const float* Wp   = (const float*)d_in[6];
    const float* bp   = (const float*)d_in[7];
    const float* Wc   = (const float*)d_in[8];
    const float* bc   = (const float*)d_in[9];

    float* out      = (float*)d_out;
    float* out_pred = out;                                  // [64,32,5000]
    float* out_attn = out + (size_t)STEPS * BB * VV;        // [64,32,1024]

    float *xT, *hT, *cT, *gT, *ctxT, *hidT;
    cudaGetSymbolAddress((void**)&xT,   g_xT);
    cudaGetSymbolAddress((void**)&hT,   g_hT);
    cudaGetSymbolAddress((void**)&cT,   g_cT);
    cudaGetSymbolAddress((void**)&gT,   g_gatesT);
    cudaGetSymbolAddress((void**)&ctxT, g_ctxT);
    cudaGetSymbolAddress((void**)&hidT, g_hidT);

    init_kernel<<<128, 256>>>(emb, lf);

    for (int s = 0; s < STEPS; s++) {
        // LSTM gates: [2048,32] = W_ih @ xT + W_hh @ hT + biases
        gemm4_kernel<<<256, 64>>>(W_ih, KX, W_hh, HH, KX, HH,
                                  xT, hT, b_ih, b_hh,
                                  gT, nullptr, 0, 4 * HH, 0);
        lstm_gate_kernel<<<64, 256>>>();

        attention_kernel<<<128, 256>>>(lf, out_attn + (size_t)s * BB * TT);

        // predict_hid: relu(Wp @ [h; ctx] + bp)
        gemm1_kernel<<<64, 256>>>(Wp, hT, ctxT, bp, hidT);

        // logits: Wc @ hid + bc  -> written row-major into d_out
        gemm4_kernel<<<625, 64>>>(Wc, 512, nullptr, 0, 512, 0,
                                  hidT, nullptr, bc, nullptr,
                                  nullptr, out_pred + (size_t)s * BB * VV, VV, VV, 0);

        lsm_argmax_kernel<<<32, 256>>>(out_pred + (size_t)s * BB * VV);
        next_input_kernel<<<128, 256>>>(emb);
    }
}

// round 3
// speedup vs baseline: 2.6041x; 2.6041x over previous
#include <cuda_runtime.h>
#include <math.h>

#define BB 32
#define TT 1024
#define FF 512
#define EE 512
#define HH 512
#define VV 5000
#define STEPS 64
#define JPAD 5008          // padded logits row

// ---------------- persistent device state ----------------
// activation buffer, transposed [k][b]: [emb(512) | ctx(512) | h(512)]
__device__ float g_actT[1536 * BB];
// [h(512) | ctx(512)] for predict_hid
__device__ float g_hcT[1024 * BB];
__device__ float g_cT[HH * BB];
__device__ float g_gatesP[4][2048 * BB];     // K-chunk partials, [j][b]
__device__ float g_hidT[512 * BB];
__device__ float g_logitsP[2][BB * JPAD];    // [part][b][j]
__device__ float g_eBuf[BB * TT];            // raw energies, head 3 only
__device__ float g_mP[4 * 128];              // [part][b*4+h]
__device__ float g_sP[4 * 128];
__device__ float g_ctxP[4][128 * 128];       // [part][(b*4+h)*128 + d]

// ---------------- init: act = [emb[0] | lf[:,0,:] | 0], c = 0 ----------------
__global__ void init_kernel(const float* __restrict__ emb, const float* __restrict__ lf)
{
    int idx = blockIdx.x * blockDim.x + threadIdx.x;   // 1536*32
    if (idx >= 1536 * BB) return;
    int b = idx & 31, k = idx >> 5;
    float v;
    if (k < 512)       v = emb[k];
    else if (k < 1024) v = lf[(size_t)b * TT * FF + (k - 512)];
    else             { v = 0.f; g_cT[(k - 1024) * BB + b] = 0.f; }
    g_actT[idx] = v;
}

// ---------------- gates GEMM, K-split x4 ----------------
// part p handles k in [p*384, p*384+384); weight row j: k<1024 -> W_ih, else W_hh
__global__ void gates_gemm_kernel(const float* __restrict__ W_ih,
                                  const float* __restrict__ W_hh)
{
    __shared__ float ws[16 * 384];
    const int j0 = blockIdx.x * 16;
    const int base = blockIdx.y * 384;
    for (int idx = threadIdx.x; idx < 16 * 384; idx += 128) {
        int r = idx / 384, kk = idx - r * 384;
        int k = base + kk, j = j0 + r;
        ws[idx] = (k < 1024) ? W_ih[(size_t)j * 1024 + k]
                             : W_hh[(size_t)j * 512 + (k - 1024)];
    }
    __syncthreads();

    int bg = threadIdx.x & 7, jj = threadIdx.x >> 3;
    const float* wr = ws + jj * 384;
    const float4* xv = (const float4*)g_actT;
    float ax = 0.f, ay = 0.f, az = 0.f, aw = 0.f;
    #pragma unroll 4
    for (int kk = 0; kk < 384; kk++) {
        float w = wr[kk];
        float4 x = xv[(base + kk) * 8 + bg];
        ax = fmaf(w, x.x, ax); ay = fmaf(w, x.y, ay);
        az = fmaf(w, x.z, az); aw = fmaf(w, x.w, aw);
    }
    ((float4*)g_gatesP[blockIdx.y])[(j0 + jj) * 8 + bg] = make_float4(ax, ay, az, aw);
}

// ---------------- LSTM pointwise: reduce gate partials, update h,c ----------
__global__ void lstm_pointwise_kernel(const float* __restrict__ b_ih,
                                      const float* __restrict__ b_hh)
{
    int idx = blockIdx.x * blockDim.x + threadIdx.x;   // 512*32
    if (idx >= HH * BB) return;
    int b = idx & 31, i = idx >> 5;
    float g4[4];
    #pragma unroll
    for (int g = 0; g < 4; g++) {
        int j = g * 512 + i;
        float v = b_ih[j] + b_hh[j];
        #pragma unroll
        for (int p = 0; p < 4; p++) v += g_gatesP[p][j * BB + b];
        g4[g] = v;
    }
    float si = 1.f / (1.f + __expf(-g4[0]));
    float sf = 1.f / (1.f + __expf(-g4[1]));
    float tg = tanhf(g4[2]);
    float so = 1.f / (1.f + __expf(-g4[3]));
    float c = sf * g_cT[idx] + si * tg;
    g_cT[idx] = c;
    float h = so * tanhf(c);
    g_actT[(1024 + i) * BB + b] = h;
    g_hcT[i * BB + b] = h;
}

// ---------------- attention partials: split T x4, local softmax ------------
__global__ void attn_part_kernel(const float* __restrict__ lf)
{
    int b = blockIdx.x & 31, hh = blockIdx.x >> 5;
    int part = blockIdx.y;
    int t0 = part * 256;
    __shared__ float e_s[256];
    __shared__ float red[8];
    __shared__ float csh[256];
    int tid = threadIdx.x, lane = tid & 31, wid = tid >> 5;

    int dbase = hh * 128 + lane * 4;
    float4 ds;
    ds.x = g_actT[(1024 + dbase + 0) * BB + b];
    ds.y = g_actT[(1024 + dbase + 1) * BB + b];
    ds.z = g_actT[(1024 + dbase + 2) * BB + b];
    ds.w = g_actT[(1024 + dbase + 3) * BB + b];

    // energy: one warp per t
    const float4* lfb = (const float4*)(lf + (size_t)b * TT * FF + hh * 128);
    for (int tt = wid; tt < 256; tt += 8) {
        int t = t0 + tt;
        float4 v = lfb[(size_t)t * 128 + lane];
        float p = ds.x * v.x + ds.y * v.y + ds.z * v.z + ds.w * v.w;
        #pragma unroll
        for (int off = 16; off; off >>= 1) p += __shfl_xor_sync(0xffffffffu, p, off);
        if (lane == 0) {
            e_s[tt] = p;
            if (hh == 3) g_eBuf[b * TT + t] = p;
        }
    }
    __syncthreads();

    // local max
    float m = e_s[tid];
    #pragma unroll
    for (int off = 16; off; off >>= 1) m = fmaxf(m, __shfl_xor_sync(0xffffffffu, m, off));
    if (lane == 0) red[wid] = m;
    __syncthreads();
    float mm = fmaxf(fmaxf(fmaxf(red[0], red[1]), fmaxf(red[2], red[3])),
                     fmaxf(fmaxf(red[4], red[5]), fmaxf(red[6], red[7])));
    __syncthreads();

    // exp + local sum
    float p = __expf(e_s[tid] - mm);
    e_s[tid] = p;
    #pragma unroll
    for (int off = 16; off; off >>= 1) p += __shfl_xor_sync(0xffffffffu, p, off);
    if (lane == 0) red[wid] = p;
    __syncthreads();
    float ssum = red[0] + red[1] + red[2] + red[3] + red[4] + red[5] + red[6] + red[7];

    int bh = b * 4 + hh;
    if (tid == 0) { g_mP[part * 128 + bh] = mm; g_sP[part * 128 + bh] = ssum; }

    // context partial (lines are L1-resident from the energy pass)
    int d = tid & 127, half = tid >> 7;
    const float* lfp = lf + (size_t)b * TT * FF + hh * 128 + d;
    float acc = 0.f;
    int tt0 = half * 128;
    #pragma unroll 4
    for (int tt = tt0; tt < tt0 + 128; tt++)
        acc = fmaf(e_s[tt], lfp[(size_t)(t0 + tt) * FF], acc);
    csh[tid] = acc;
    __syncthreads();
    if (tid < 128)
        g_ctxP[part][bh * 128 + tid] = csh[tid] + csh[tid + 128];
}

// ---------------- attention combine: global softmax, write ctx + scores ----
__global__ void attn_combine_kernel(float* __restrict__ attn_out)
{
    int b = blockIdx.x & 31, hh = blockIdx.x >> 5;
    int bh = b * 4 + hh;
    int tid = threadIdx.x;   // 128 = d

    float m0 = g_mP[0 * 128 + bh], m1 = g_mP[1 * 128 + bh];
    float m2 = g_mP[2 * 128 + bh], m3 = g_mP[3 * 128 + bh];
    float M = fmaxf(fmaxf(m0, m1), fmaxf(m2, m3));
    float w0 = __expf(m0 - M), w1 = __expf(m1 - M);
    float w2 = __expf(m2 - M), w3 = __expf(m3 - M);
    float S = g_sP[0 * 128 + bh] * w0 + g_sP[1 * 128 + bh] * w1
            + g_sP[2 * 128 + bh] * w2 + g_sP[3 * 128 + bh] * w3;
    float inv = 1.f / S;

    float ctx = (g_ctxP[0][bh * 128 + tid] * w0 + g_ctxP[1][bh * 128 + tid] * w1
               + g_ctxP[2][bh * 128 + tid] * w2 + g_ctxP[3][bh * 128 + tid] * w3) * inv;
    int d = hh * 128 + tid;
    g_actT[(512 + d) * BB + b] = ctx;   // next rnn input ctx slot
    g_hcT[(512 + d) * BB + b] = ctx;    // predict_hid input

    if (hh == 3) {
        for (int t = tid; t < TT; t += 128)
            attn_out[(size_t)b * TT + t] = __expf(g_eBuf[b * TT + t] - M) * inv;
    }
}

// ---------------- predict_hid: thread per (j,b), relu ----------------------
__global__ void hid_gemm_kernel(const float* __restrict__ Wp, const float* __restrict__ bp)
{
    int wid = threadIdx.x >> 5, lane = threadIdx.x & 31;   // lane = b
    int j = blockIdx.x * 8 + wid;
    const float4* wv = (const float4*)(Wp + (size_t)j * 1024);
    float acc = 0.f;
    #pragma unroll 4
    for (int k4 = 0; k4 < 256; k4++) {
        float4 w = wv[k4];
        int k = k4 * 4;
        acc = fmaf(w.x, g_hcT[(k + 0) * BB + lane], acc);
        acc = fmaf(w.y, g_hcT[(k + 1) * BB + lane], acc);
        acc = fmaf(w.z, g_hcT[(k + 2) * BB + lane], acc);
        acc = fmaf(w.w, g_hcT[(k + 3) * BB + lane], acc);
    }
    acc += bp[j];
    g_hidT[j * BB + lane] = fmaxf(acc, 0.f);
}

// ---------------- logits GEMM, K-split x2, 16 rows/block --------------------
__global__ void logits_gemm_kernel(const float* __restrict__ Wc)
{
    __shared__ float ws[16 * 256];
    const int j0 = blockIdx.x * 16;
    const int base = blockIdx.y * 256;
    for (int idx = threadIdx.x; idx < 16 * 256; idx += 128) {
        int r = idx >> 8, kk = idx & 255;
        int j = j0 + r;
        ws[idx] = (j < VV) ? Wc[(size_t)j * 512 + base + kk] : 0.f;
    }
    __syncthreads();

    int bg = threadIdx.x & 7, jj = threadIdx.x >> 3;
    int j = j0 + jj;
    const float* wr = ws + jj * 256;
    const float4* xv = (const float4*)g_hidT;
    float ax = 0.f, ay = 0.f, az = 0.f, aw = 0.f;
    #pragma unroll 4
    for (int kk = 0; kk < 256; kk++) {
        float w = wr[kk];
        float4 x = xv[(base + kk) * 8 + bg];
        ax = fmaf(w, x.x, ax); ay = fmaf(w, x.y, ay);
        az = fmaf(w, x.z, az); aw = fmaf(w, x.w, aw);
    }
    if (j < VV) {
        float* dst = g_logitsP[blockIdx.y];
        int b0 = bg * 4;
        dst[(size_t)(b0 + 0) * JPAD + j] = ax;
        dst[(size_t)(b0 + 1) * JPAD + j] = ay;
        dst[(size_t)(b0 + 2) * JPAD + j] = az;
        dst[(size_t)(b0 + 3) * JPAD + j] = aw;
    }
}

// ------- log_softmax + argmax + write pred row + gather next embedding -----
__global__ void lsm_kernel(const float* __restrict__ bc, const float* __restrict__ emb,
                           float* __restrict__ out_pred)
{
    int b = blockIdx.x;
    int tid = threadIdx.x;
    __shared__ float v_s[VV];
    __shared__ float sv[256];
    __shared__ int   si[256];
    __shared__ int   tok_s;

    const float* p0 = g_logitsP[0] + (size_t)b * JPAD;
    const float* p1 = g_logitsP[1] + (size_t)b * JPAD;
    for (int j = tid; j < VV; j += 256) v_s[j] = p0[j] + p1[j] + bc[j];
    __syncthreads();

    // argmax / max (first-index ties)
    float m = -1e30f; int mi = VV;
    for (int j = tid; j < VV; j += 256) {
        float v = v_s[j];
        if (v > m) { m = v; mi = j; }
    }
    sv[tid] = m; si[tid] = mi; __syncthreads();
    for (int st = 128; st; st >>= 1) {
        if (tid < st) {
            float v2 = sv[tid + st]; int i2 = si[tid + st];
            if (v2 > sv[tid] || (v2 == sv[tid] && i2 < si[tid])) { sv[tid] = v2; si[tid] = i2; }
        }
        __syncthreads();
    }
    float mm = sv[0];
    if (tid == 0) tok_s = si[0];
    __syncthreads();

    float s = 0.f;
    for (int j = tid; j < VV; j += 256) s += __expf(v_s[j] - mm);
    sv[tid] = s; __syncthreads();
    for (int st = 128; st; st >>= 1) { if (tid < st) sv[tid] += sv[tid + st]; __syncthreads(); }
    float lse = mm + logf(sv[0]);

    float* row = out_pred + (size_t)b * VV;
    for (int j = tid; j < VV; j += 256) row[j] = v_s[j] - lse;

    // next-step embedding into activation buffer
    int tok = tok_s;
    for (int k = tid; k < 512; k += 256)
        g_actT[k * BB + b] = emb[(size_t)tok * EE + k];
}

// ---------------- launcher ----------------
extern "C" void kernel_launch(void* const* d_in, const int* in_sizes, int n_in,
                              void* d_out, int out_size)
{
    const float* lf   = (const float*)d_in[0];
    const float* emb  = (const float*)d_in[1];
    const float* W_ih = (const float*)d_in[2];
    const float* W_hh = (const float*)d_in[3];
    const float* b_ih = (const float*)d_in[4];
    const float* b_hh = (const float*)d_in[5];
    const float* Wp   = (const float*)d_in[6];
    const float* bp   = (const float*)d_in[7];
    const float* Wc   = (const float*)d_in[8];
    const float* bc   = (const float*)d_in[9];

    float* out      = (float*)d_out;
    float* out_pred = out;                               // [64,32,5000]
    float* out_attn = out + (size_t)STEPS * BB * VV;     // [64,32,1024]

    init_kernel<<<192, 256>>>(emb, lf);

    for (int s = 0; s < STEPS; s++) {
        gates_gemm_kernel<<<dim3(128, 4), 128>>>(W_ih, W_hh);
        lstm_pointwise_kernel<<<64, 256>>>(b_ih, b_hh);
        attn_part_kernel<<<dim3(128, 4), 256>>>(lf);
        attn_combine_kernel<<<128, 128>>>(out_attn + (size_t)s * BB * TT);
        hid_gemm_kernel<<<64, 256>>>(Wp, bp);
        logits_gemm_kernel<<<dim3(313, 2), 128>>>(Wc);
        lsm_kernel<<<32, 256>>>(bc, emb, out_pred + (size_t)s * BB * VV);
    }
}

// round 4
// speedup vs baseline: 2.9496x; 1.1327x over previous
#include <cuda_runtime.h>
#include <math.h>

#define BB 32
#define TT 1024
#define FF 512
#define EE 512
#define HH 512
#define VV 5000
#define STEPS 64
#define JPAD 5008
#define NP 16            // attention T-parts
#define TCH 64           // t-chunk per part

// ---------------- persistent device state ----------------
__device__ float g_actT[1536 * BB];          // [emb|ctx|h] transposed [k][b]
__device__ float g_hcT[1024 * BB];           // [h|ctx] transposed
__device__ float g_hRow[BB * 512];           // h row-major [b][i]
__device__ float g_cT[HH * BB];
__device__ float g_gatesP[4][2048 * BB];
__device__ float g_hidT[512 * BB];
__device__ float g_logitsP[2][BB * JPAD];
__device__ float g_eBuf[BB * TT];
__device__ float g_mP[NP * 128];
__device__ float g_sP[NP * 128];
__device__ float g_ctxP[NP][128 * 128];

// ---------------- init ----------------
__global__ void init_kernel(const float* __restrict__ emb, const float* __restrict__ lf)
{
    int idx = blockIdx.x * blockDim.x + threadIdx.x;
    if (idx >= 1536 * BB) return;
    int b = idx & 31, k = idx >> 5;
    float v;
    if (k < 512)       v = emb[k];
    else if (k < 1024) v = lf[(size_t)b * TT * FF + (k - 512)];
    else             { v = 0.f; g_cT[(k - 1024) * BB + b] = 0.f; }
    g_actT[idx] = v;
}

// ---------------- gates GEMM, K-split x4, padded smem ----------------
__global__ void gates_gemm_kernel(const float* __restrict__ W_ih,
                                  const float* __restrict__ W_hh)
{
    __shared__ float ws[16 * 385];
    const int j0 = blockIdx.x * 16;
    const int base = blockIdx.y * 384;
    for (int idx = threadIdx.x; idx < 16 * 384; idx += 128) {
        int r = idx / 384, kk = idx - r * 384;
        int k = base + kk, j = j0 + r;
        ws[r * 385 + kk] = (k < 1024) ? W_ih[(size_t)j * 1024 + k]
                                      : W_hh[(size_t)j * 512 + (k - 1024)];
    }
    __syncthreads();

    int bg = threadIdx.x & 7, jj = threadIdx.x >> 3;
    const float* wr = ws + jj * 385;
    const float4* xv = (const float4*)g_actT;
    float ax = 0.f, ay = 0.f, az = 0.f, aw = 0.f;
    #pragma unroll 8
    for (int kk = 0; kk < 384; kk++) {
        float w = wr[kk];
        float4 x = xv[(base + kk) * 8 + bg];
        ax = fmaf(w, x.x, ax); ay = fmaf(w, x.y, ay);
        az = fmaf(w, x.z, az); aw = fmaf(w, x.w, aw);
    }
    ((float4*)g_gatesP[blockIdx.y])[(j0 + jj) * 8 + bg] = make_float4(ax, ay, az, aw);
}

// ---------------- LSTM pointwise ----------------
__global__ void lstm_pointwise_kernel(const float* __restrict__ b_ih,
                                      const float* __restrict__ b_hh)
{
    int idx = blockIdx.x * blockDim.x + threadIdx.x;
    if (idx >= HH * BB) return;
    int b = idx & 31, i = idx >> 5;
    float g4[4];
    #pragma unroll
    for (int g = 0; g < 4; g++) {
        int j = g * 512 + i;
        float v = b_ih[j] + b_hh[j];
        #pragma unroll
        for (int p = 0; p < 4; p++) v += g_gatesP[p][j * BB + b];
        g4[g] = v;
    }
    float si = 1.f / (1.f + __expf(-g4[0]));
    float sf = 1.f / (1.f + __expf(-g4[1]));
    float tg = tanhf(g4[2]);
    float so = 1.f / (1.f + __expf(-g4[3]));
    float c = sf * g_cT[idx] + si * tg;
    g_cT[idx] = c;
    float h = so * tanhf(c);
    g_actT[(1024 + i) * BB + b] = h;
    g_hcT[i * BB + b] = h;
    g_hRow[b * 512 + i] = h;
}

// ---------------- attention partials: smem-transposed tile, no shuffles ----
__global__ void attn_part_kernel(const float* __restrict__ lf)
{
    __shared__ float tile[TCH * 129];   // odd stride: row & column reads conflict-free
    __shared__ float ds_s[128];
    __shared__ float ep[4][TCH];
    __shared__ float e_s[TCH];
    __shared__ float red2[8];
    __shared__ float csh[256];

    int b = blockIdx.x & 31, hh = blockIdx.x >> 5;
    int part = blockIdx.y;
    int t0 = part * TCH;
    int tid = threadIdx.x;

    if (tid < 128) ds_s[tid] = g_hRow[b * 512 + hh * 128 + tid];

    // stage tile: 64 t x 128 d
    const float4* src = (const float4*)(lf + ((size_t)b * TT + t0) * FF + hh * 128);
    for (int idx = tid; idx < TCH * 32; idx += 256) {
        int t = idx >> 5, c = idx & 31;
        float4 v = src[(size_t)t * 128 + c];
        float* dst = &tile[t * 129 + c * 4];
        dst[0] = v.x; dst[1] = v.y; dst[2] = v.z; dst[3] = v.w;
    }
    __syncthreads();

    // energy partials: thread (dg, t), plain FMA over 32 d
    {
        int t = tid & 63, dg = tid >> 6;
        const float* tr = &tile[t * 129 + dg * 32];
        const float* dsp = &ds_s[dg * 32];
        float a = 0.f;
        #pragma unroll
        for (int d = 0; d < 32; d++) a = fmaf(dsp[d], tr[d], a);
        ep[dg][t] = a;
    }
    __syncthreads();

    if (tid < TCH) {
        float e = ep[0][tid] + ep[1][tid] + ep[2][tid] + ep[3][tid];
        e_s[tid] = e;
        if (hh == 3) g_eBuf[b * TT + t0 + tid] = e;
    }
    __syncthreads();

    if (tid < 64) {
        float m = e_s[tid];
        #pragma unroll
        for (int off = 16; off; off >>= 1) m = fmaxf(m, __shfl_xor_sync(~0u, m, off));
        if ((tid & 31) == 0) red2[tid >> 5] = m;
    }
    __syncthreads();
    float mm = fmaxf(red2[0], red2[1]);
    if (tid < 64) {
        float p = __expf(e_s[tid] - mm);
        e_s[tid] = p;
        #pragma unroll
        for (int off = 16; off; off >>= 1) p += __shfl_xor_sync(~0u, p, off);
        if ((tid & 31) == 0) red2[4 + (tid >> 5)] = p;
    }
    __syncthreads();
    int bh = b * 4 + hh;
    if (tid == 0) {
        g_mP[part * 128 + bh] = mm;
        g_sP[part * 128 + bh] = red2[4] + red2[5];
    }

    // context partial: thread (d, th), column reads conflict-free
    {
        int d = tid & 127, th = tid >> 7;
        const float* col = &tile[th * 32 * 129 + d];
        const float* ps = &e_s[th * 32];
        float acc = 0.f;
        #pragma unroll
        for (int t = 0; t < 32; t++) acc = fmaf(ps[t], col[t * 129], acc);
        csh[tid] = acc;
    }
    __syncthreads();
    if (tid < 128)
        g_ctxP[part][bh * 128 + tid] = csh[tid] + csh[tid + 128];
}

// ---------------- attention combine ----------------
__global__ void attn_combine_kernel(float* __restrict__ attn_out)
{
    int b = blockIdx.x & 31, hh = blockIdx.x >> 5;
    int bh = b * 4 + hh;
    int tid = threadIdx.x;   // 128
    __shared__ float mp_s[NP], sp_s[NP];
    if (tid < NP) { mp_s[tid] = g_mP[tid * 128 + bh]; sp_s[tid] = g_sP[tid * 128 + bh]; }
    __syncthreads();

    float M = -1e30f;
    #pragma unroll
    for (int p = 0; p < NP; p++) M = fmaxf(M, mp_s[p]);
    float S = 0.f, w[NP];
    #pragma unroll
    for (int p = 0; p < NP; p++) { w[p] = __expf(mp_s[p] - M); S += sp_s[p] * w[p]; }
    float inv = 1.f / S;

    float ctx = 0.f;
    #pragma unroll
    for (int p = 0; p < NP; p++) ctx = fmaf(g_ctxP[p][bh * 128 + tid], w[p], ctx);
    ctx *= inv;
    int d = hh * 128 + tid;
    g_actT[(512 + d) * BB + b] = ctx;
    g_hcT[(512 + d) * BB + b] = ctx;

    if (hh == 3) {
        for (int t = tid; t < TT; t += 128)
            attn_out[(size_t)b * TT + t] = __expf(g_eBuf[b * TT + t] - M) * inv;
    }
}

// ---------------- predict_hid: warp per (j, K-half) ----------------
__global__ void hid_gemm_kernel(const float* __restrict__ Wp, const float* __restrict__ bp)
{
    __shared__ float ph[8][32];
    int wid = threadIdx.x >> 5, lane = threadIdx.x & 31;
    int jj = wid >> 1, half = wid & 1;
    int j = blockIdx.x * 4 + jj;
    const float4* wv = (const float4*)(Wp + (size_t)j * 1024 + half * 512);
    const float* x = g_hcT + half * 512 * BB;
    float acc = 0.f;
    #pragma unroll 8
    for (int k4 = 0; k4 < 128; k4++) {
        float4 wq = wv[k4];
        int k = k4 * 4;
        acc = fmaf(wq.x, x[(k + 0) * BB + lane], acc);
        acc = fmaf(wq.y, x[(k + 1) * BB + lane], acc);
        acc = fmaf(wq.z, x[(k + 2) * BB + lane], acc);
        acc = fmaf(wq.w, x[(k + 3) * BB + lane], acc);
    }
    ph[wid][lane] = acc;
    __syncthreads();
    if (wid < 4) {
        int j2 = blockIdx.x * 4 + wid;
        float v = ph[wid * 2][lane] + ph[wid * 2 + 1][lane] + bp[j2];
        g_hidT[j2 * BB + lane] = fmaxf(v, 0.f);
    }
}

// ---------------- logits GEMM, K-split x2, padded smem ----------------
__global__ void logits_gemm_kernel(const float* __restrict__ Wc)
{
    __shared__ float ws[16 * 257];
    const int j0 = blockIdx.x * 16;
    const int base = blockIdx.y * 256;
    for (int idx = threadIdx.x; idx < 16 * 256; idx += 128) {
        int r = idx >> 8, kk = idx & 255;
        int j = j0 + r;
        ws[r * 257 + kk] = (j < VV) ? Wc[(size_t)j * 512 + base + kk] : 0.f;
    }
    __syncthreads();

    int bg = threadIdx.x & 7, jj = threadIdx.x >> 3;
    int j = j0 + jj;
    const float* wr = ws + jj * 257;
    const float4* xv = (const float4*)g_hidT;
    float ax = 0.f, ay = 0.f, az = 0.f, aw = 0.f;
    #pragma unroll 8
    for (int kk = 0; kk < 256; kk++) {
        float w = wr[kk];
        float4 x = xv[(base + kk) * 8 + bg];
        ax = fmaf(w, x.x, ax); ay = fmaf(w, x.y, ay);
        az = fmaf(w, x.z, az); aw = fmaf(w, x.w, aw);
    }
    if (j < VV) {
        float* dst = g_logitsP[blockIdx.y];
        int b0 = bg * 4;
        dst[(size_t)(b0 + 0) * JPAD + j] = ax;
        dst[(size_t)(b0 + 1) * JPAD + j] = ay;
        dst[(size_t)(b0 + 2) * JPAD + j] = az;
        dst[(size_t)(b0 + 3) * JPAD + j] = aw;
    }
}

// ------- log_softmax + argmax + pred row + next embedding -----
__global__ void lsm_kernel(const float* __restrict__ bc, const float* __restrict__ emb,
                           float* __restrict__ out_pred)
{
    int b = blockIdx.x;
    int tid = threadIdx.x;   // 512
    __shared__ float v_s[VV];
    __shared__ float sv[512];
    __shared__ int   si[512];
    __shared__ int   tok_s;

    const float4* p0 = (const float4*)(g_logitsP[0] + (size_t)b * JPAD);
    const float4* p1 = (const float4*)(g_logitsP[1] + (size_t)b * JPAD);
    const float4* bcv = (const float4*)bc;
    for (int j4 = tid; j4 < VV / 4; j4 += 512) {
        float4 a = p0[j4], c = p1[j4], d = bcv[j4];
        float4 r;
        r.x = a.x + c.x + d.x; r.y = a.y + c.y + d.y;
        r.z = a.z + c.z + d.z; r.w = a.w + c.w + d.w;
        ((float4*)v_s)[j4] = r;
    }
    __syncthreads();

    float m = -1e30f; int mi = VV;
    for (int j = tid; j < VV; j += 512) {
        float v = v_s[j];
        if (v > m) { m = v; mi = j; }
    }
    sv[tid] = m; si[tid] = mi; __syncthreads();
    for (int st = 256; st; st >>= 1) {
        if (tid < st) {
            float v2 = sv[tid + st]; int i2 = si[tid + st];
            if (v2 > sv[tid] || (v2 == sv[tid] && i2 < si[tid])) { sv[tid] = v2; si[tid] = i2; }
        }
        __syncthreads();
    }
    float mm = sv[0];
    if (tid == 0) tok_s = si[0];
    __syncthreads();

    float s = 0.f;
    for (int j = tid; j < VV; j += 512) s += __expf(v_s[j] - mm);
    sv[tid] = s; __syncthreads();
    for (int st = 256; st; st >>= 1) { if (tid < st) sv[tid] += sv[tid + st]; __syncthreads(); }
    float lse = mm + logf(sv[0]);

    float4* row = (float4*)(out_pred + (size_t)b * VV);
    for (int j4 = tid; j4 < VV / 4; j4 += 512) {
        float4 v = ((float4*)v_s)[j4];
        v.x -= lse; v.y -= lse; v.z -= lse; v.w -= lse;
        row[j4] = v;
    }

    int tok = tok_s;
    if (tid < 512) g_actT[tid * BB + b] = emb[(size_t)tok * EE + tid];
}

// ---------------- launcher ----------------
extern "C" void kernel_launch(void* const* d_in, const int* in_sizes, int n_in,
                              void* d_out, int out_size)
{
    const float* lf   = (const float*)d_in[0];
    const float* emb  = (const float*)d_in[1];
    const float* W_ih = (const float*)d_in[2];
    const float* W_hh = (const float*)d_in[3];
    const float* b_ih = (const float*)d_in[4];
    const float* b_hh = (const float*)d_in[5];
    const float* Wp   = (const float*)d_in[6];
    const float* bp   = (const float*)d_in[7];
    const float* Wc   = (const float*)d_in[8];
    const float* bc   = (const float*)d_in[9];

    float* out      = (float*)d_out;
    float* out_pred = out;
    float* out_attn = out + (size_t)STEPS * BB * VV;

    init_kernel<<<192, 256>>>(emb, lf);

    for (int s = 0; s < STEPS; s++) {
        gates_gemm_kernel<<<dim3(128, 4), 128>>>(W_ih, W_hh);
        lstm_pointwise_kernel<<<64, 256>>>(b_ih, b_hh);
        attn_part_kernel<<<dim3(128, NP), 256>>>(lf);
        attn_combine_kernel<<<128, 128>>>(out_attn + (size_t)s * BB * TT);
        hid_gemm_kernel<<<128, 256>>>(Wp, bp);
        logits_gemm_kernel<<<dim3(313, 2), 128>>>(Wc);
        lsm_kernel<<<32, 512>>>(bc, emb, out_pred + (size_t)s * BB * VV);
    }
}

// round 5
// speedup vs baseline: 2.9684x; 1.0064x over previous
#include <cuda_runtime.h>
#include <math.h>

#define BB 32
#define TT 1024
#define FF 512
#define EE 512
#define HH 512
#define VV 5000
#define STEPS 64
#define JPAD 5008
#define NP 16            // attention T-parts
#define TCH 64           // t-chunk per part

// ---------------- persistent device state ----------------
__device__ float g_actT[1536 * BB];          // [emb|ctx|h] transposed [k][b]
__device__ float g_hcT[1024 * BB];           // [h|ctx] transposed
__device__ float g_hRow[BB * 512];           // h row-major [b][i]
__device__ float g_cT[HH * BB];
__device__ float g_gatesP[4][2048 * BB];
__device__ float g_hidT[512 * BB];
__device__ float g_logitsP[2][BB * JPAD];
__device__ float g_eBuf[BB * TT];
__device__ float g_mP[NP * 128];
__device__ float g_sP[NP * 128];
__device__ float g_ctxP[NP][128 * 128];

// ---------------- init ----------------
__global__ void init_kernel(const float* __restrict__ emb, const float* __restrict__ lf)
{
    int idx = blockIdx.x * blockDim.x + threadIdx.x;
    if (idx >= 1536 * BB) return;
    int b = idx & 31, k = idx >> 5;
    float v;
    if (k < 512)       v = emb[k];
    else if (k < 1024) v = lf[(size_t)b * TT * FF + (k - 512)];
    else             { v = 0.f; g_cT[(k - 1024) * BB + b] = 0.f; }
    g_actT[idx] = v;
}

// ---------------- gates GEMM, K-split x4, padded smem ----------------
__global__ void gates_gemm_kernel(const float* __restrict__ W_ih,
                                  const float* __restrict__ W_hh)
{
    __shared__ float ws[16 * 385];
    const int j0 = blockIdx.x * 16;
    const int base = blockIdx.y * 384;
    for (int idx = threadIdx.x; idx < 16 * 384; idx += 128) {
        int r = idx / 384, kk = idx - r * 384;
        int k = base + kk, j = j0 + r;
        ws[r * 385 + kk] = (k < 1024) ? W_ih[(size_t)j * 1024 + k]
                                      : W_hh[(size_t)j * 512 + (k - 1024)];
    }
    __syncthreads();

    int bg = threadIdx.x & 7, jj = threadIdx.x >> 3;
    const float* wr = ws + jj * 385;
    const float4* xv = (const float4*)g_actT;
    float ax = 0.f, ay = 0.f, az = 0.f, aw = 0.f;
    #pragma unroll 8
    for (int kk = 0; kk < 384; kk++) {
        float w = wr[kk];
        float4 x = xv[(base + kk) * 8 + bg];
        ax = fmaf(w, x.x, ax); ay = fmaf(w, x.y, ay);
        az = fmaf(w, x.z, az); aw = fmaf(w, x.w, aw);
    }
    ((float4*)g_gatesP[blockIdx.y])[(j0 + jj) * 8 + bg] = make_float4(ax, ay, az, aw);
}

// ---------------- LSTM pointwise ----------------
__global__ void lstm_pointwise_kernel(const float* __restrict__ b_ih,
                                      const float* __restrict__ b_hh)
{
    int idx = blockIdx.x * blockDim.x + threadIdx.x;
    if (idx >= HH * BB) return;
    int b = idx & 31, i = idx >> 5;
    float g4[4];
    #pragma unroll
    for (int g = 0; g < 4; g++) {
        int j = g * 512 + i;
        float v = b_ih[j] + b_hh[j];
        #pragma unroll
        for (int p = 0; p < 4; p++) v += g_gatesP[p][j * BB + b];
        g4[g] = v;
    }
    float si = 1.f / (1.f + __expf(-g4[0]));
    float sf = 1.f / (1.f + __expf(-g4[1]));
    float tg = tanhf(g4[2]);
    float so = 1.f / (1.f + __expf(-g4[3]));
    float c = sf * g_cT[idx] + si * tg;
    g_cT[idx] = c;
    float h = so * tanhf(c);
    g_actT[(1024 + i) * BB + b] = h;
    g_hcT[i * BB + b] = h;
    g_hRow[b * 512 + i] = h;
}

// ---------------- attention partials: smem-transposed tile, no shuffles ----
__global__ void attn_part_kernel(const float* __restrict__ lf)
{
    __shared__ float tile[TCH * 129];   // odd stride: row & column reads conflict-free
    __shared__ float ds_s[128];
    __shared__ float ep[4][TCH];
    __shared__ float e_s[TCH];
    __shared__ float red2[8];
    __shared__ float csh[256];

    int b = blockIdx.x & 31, hh = blockIdx.x >> 5;
    int part = blockIdx.y;
    int t0 = part * TCH;
    int tid = threadIdx.x;

    if (tid < 128) ds_s[tid] = g_hRow[b * 512 + hh * 128 + tid];

    // stage tile: 64 t x 128 d
    const float4* src = (const float4*)(lf + ((size_t)b * TT + t0) * FF + hh * 128);
    for (int idx = tid; idx < TCH * 32; idx += 256) {
        int t = idx >> 5, c = idx & 31;
        float4 v = src[(size_t)t * 128 + c];
        float* dst = &tile[t * 129 + c * 4];
        dst[0] = v.x; dst[1] = v.y; dst[2] = v.z; dst[3] = v.w;
    }
    __syncthreads();

    // energy partials: thread (dg, t), plain FMA over 32 d
    {
        int t = tid & 63, dg = tid >> 6;
        const float* tr = &tile[t * 129 + dg * 32];
        const float* dsp = &ds_s[dg * 32];
        float a = 0.f;
        #pragma unroll
        for (int d = 0; d < 32; d++) a = fmaf(dsp[d], tr[d], a);
        ep[dg][t] = a;
    }
    __syncthreads();

    if (tid < TCH) {
        float e = ep[0][tid] + ep[1][tid] + ep[2][tid] + ep[3][tid];
        e_s[tid] = e;
        if (hh == 3) g_eBuf[b * TT + t0 + tid] = e;
    }
    __syncthreads();

    if (tid < 64) {
        float m = e_s[tid];
        #pragma unroll
        for (int off = 16; off; off >>= 1) m = fmaxf(m, __shfl_xor_sync(~0u, m, off));
        if ((tid & 31) == 0) red2[tid >> 5] = m;
    }
    __syncthreads();
    float mm = fmaxf(red2[0], red2[1]);
    if (tid < 64) {
        float p = __expf(e_s[tid] - mm);
        e_s[tid] = p;
        #pragma unroll
        for (int off = 16; off; off >>= 1) p += __shfl_xor_sync(~0u, p, off);
        if ((tid & 31) == 0) red2[4 + (tid >> 5)] = p;
    }
    __syncthreads();
    int bh = b * 4 + hh;
    if (tid == 0) {
        g_mP[part * 128 + bh] = mm;
        g_sP[part * 128 + bh] = red2[4] + red2[5];
    }

    // context partial: thread (d, th), column reads conflict-free
    {
        int d = tid & 127, th = tid >> 7;
        const float* col = &tile[th * 32 * 129 + d];
        const float* ps = &e_s[th * 32];
        float acc = 0.f;
        #pragma unroll
        for (int t = 0; t < 32; t++) acc = fmaf(ps[t], col[t * 129], acc);
        csh[tid] = acc;
    }
    __syncthreads();
    if (tid < 128)
        g_ctxP[part][bh * 128 + tid] = csh[tid] + csh[tid + 128];
}

// ---------------- attention combine ----------------
__global__ void attn_combine_kernel(float* __restrict__ attn_out)
{
    int b = blockIdx.x & 31, hh = blockIdx.x >> 5;
    int bh = b * 4 + hh;
    int tid = threadIdx.x;   // 128
    __shared__ float mp_s[NP], sp_s[NP];
    if (tid < NP) { mp_s[tid] = g_mP[tid * 128 + bh]; sp_s[tid] = g_sP[tid * 128 + bh]; }
    __syncthreads();

    float M = -1e30f;
    #pragma unroll
    for (int p = 0; p < NP; p++) M = fmaxf(M, mp_s[p]);
    float S = 0.f, w[NP];
    #pragma unroll
    for (int p = 0; p < NP; p++) { w[p] = __expf(mp_s[p] - M); S += sp_s[p] * w[p]; }
    float inv = 1.f / S;

    float ctx = 0.f;
    #pragma unroll
    for (int p = 0; p < NP; p++) ctx = fmaf(g_ctxP[p][bh * 128 + tid], w[p], ctx);
    ctx *= inv;
    int d = hh * 128 + tid;
    g_actT[(512 + d) * BB + b] = ctx;
    g_hcT[(512 + d) * BB + b] = ctx;

    if (hh == 3) {
        for (int t = tid; t < TT; t += 128)
            attn_out[(size_t)b * TT + t] = __expf(g_eBuf[b * TT + t] - M) * inv;
    }
}

// ---------------- predict_hid: warp per (j, K-half) ----------------
__global__ void hid_gemm_kernel(const float* __restrict__ Wp, const float* __restrict__ bp)
{
    __shared__ float ph[8][32];
    int wid = threadIdx.x >> 5, lane = threadIdx.x & 31;
    int jj = wid >> 1, half = wid & 1;
    int j = blockIdx.x * 4 + jj;
    const float4* wv = (const float4*)(Wp + (size_t)j * 1024 + half * 512);
    const float* x = g_hcT + half * 512 * BB;
    float acc = 0.f;
    #pragma unroll 8
    for (int k4 = 0; k4 < 128; k4++) {
        float4 wq = wv[k4];
        int k = k4 * 4;
        acc = fmaf(wq.x, x[(k + 0) * BB + lane], acc);
        acc = fmaf(wq.y, x[(k + 1) * BB + lane], acc);
        acc = fmaf(wq.z, x[(k + 2) * BB + lane], acc);
        acc = fmaf(wq.w, x[(k + 3) * BB + lane], acc);
    }
    ph[wid][lane] = acc;
    __syncthreads();
    if (wid < 4) {
        int j2 = blockIdx.x * 4 + wid;
        float v = ph[wid * 2][lane] + ph[wid * 2 + 1][lane] + bp[j2];
        g_hidT[j2 * BB + lane] = fmaxf(v, 0.f);
    }
}

// ---------------- logits GEMM, K-split x2, padded smem ----------------
__global__ void logits_gemm_kernel(const float* __restrict__ Wc)
{
    __shared__ float ws[16 * 257];
    const int j0 = blockIdx.x * 16;
    const int base = blockIdx.y * 256;
    for (int idx = threadIdx.x; idx < 16 * 256; idx += 128) {
        int r = idx >> 8, kk = idx & 255;
        int j = j0 + r;
        ws[r * 257 + kk] = (j < VV) ? Wc[(size_t)j * 512 + base + kk] : 0.f;
    }
    __syncthreads();

    int bg = threadIdx.x & 7, jj = threadIdx.x >> 3;
    int j = j0 + jj;
    const float* wr = ws + jj * 257;
    const float4* xv = (const float4*)g_hidT;
    float ax = 0.f, ay = 0.f, az = 0.f, aw = 0.f;
    #pragma unroll 8
    for (int kk = 0; kk < 256; kk++) {
        float w = wr[kk];
        float4 x = xv[(base + kk) * 8 + bg];
        ax = fmaf(w, x.x, ax); ay = fmaf(w, x.y, ay);
        az = fmaf(w, x.z, az); aw = fmaf(w, x.w, aw);
    }
    if (j < VV) {
        float* dst = g_logitsP[blockIdx.y];
        int b0 = bg * 4;
        dst[(size_t)(b0 + 0) * JPAD + j] = ax;
        dst[(size_t)(b0 + 1) * JPAD + j] = ay;
        dst[(size_t)(b0 + 2) * JPAD + j] = az;
        dst[(size_t)(b0 + 3) * JPAD + j] = aw;
    }
}

// ------- log_softmax + argmax + pred row + next embedding -----
__global__ void lsm_kernel(const float* __restrict__ bc, const float* __restrict__ emb,
                           float* __restrict__ out_pred)
{
    int b = blockIdx.x;
    int tid = threadIdx.x;   // 512
    __shared__ float v_s[VV];
    __shared__ float sv[512];
    __shared__ int   si[512];
    __shared__ int   tok_s;

    const float4* p0 = (const float4*)(g_logitsP[0] + (size_t)b * JPAD);
    const float4* p1 = (const float4*)(g_logitsP[1] + (size_t)b * JPAD);
    const float4* bcv = (const float4*)bc;
    for (int j4 = tid; j4 < VV / 4; j4 += 512) {
        float4 a = p0[j4], c = p1[j4], d = bcv[j4];
        float4 r;
        r.x = a.x + c.x + d.x; r.y = a.y + c.y + d.y;
        r.z = a.z + c.z + d.z; r.w = a.w + c.w + d.w;
        ((float4*)v_s)[j4] = r;
    }
    __syncthreads();

    float m = -1e30f; int mi = VV;
    for (int j = tid; j < VV; j += 512) {
        float v = v_s[j];
        if (v > m) { m = v; mi = j; }
    }
    sv[tid] = m; si[tid] = mi; __syncthreads();
    for (int st = 256; st; st >>= 1) {
        if (tid < st) {
            float v2 = sv[tid + st]; int i2 = si[tid + st];
            if (v2 > sv[tid] || (v2 == sv[tid] && i2 < si[tid])) { sv[tid] = v2; si[tid] = i2; }
        }
        __syncthreads();
    }
    float mm = sv[0];
    if (tid == 0) tok_s = si[0];
    __syncthreads();

    float s = 0.f;
    for (int j = tid; j < VV; j += 512) s += __expf(v_s[j] - mm);
    sv[tid] = s; __syncthreads();
    for (int st = 256; st; st >>= 1) { if (tid < st) sv[tid] += sv[tid + st]; __syncthreads(); }
    float lse = mm + logf(sv[0]);

    float4* row = (float4*)(out_pred + (size_t)b * VV);
    for (int j4 = tid; j4 < VV / 4; j4 += 512) {
        float4 v = ((float4*)v_s)[j4];
        v.x -= lse; v.y -= lse; v.z -= lse; v.w -= lse;
        row[j4] = v;
    }

    int tok = tok_s;
    if (tid < 512) g_actT[tid * BB + b] = emb[(size_t)tok * EE + tid];
}

// ---------------- launcher ----------------
extern "C" void kernel_launch(void* const* d_in, const int* in_sizes, int n_in,
                              void* d_out, int out_size)
{
    const float* lf   = (const float*)d_in[0];
    const float* emb  = (const float*)d_in[1];
    const float* W_ih = (const float*)d_in[2];
    const float* W_hh = (const float*)d_in[3];
    const float* b_ih = (const float*)d_in[4];
    const float* b_hh = (const float*)d_in[5];
    const float* Wp   = (const float*)d_in[6];
    const float* bp   = (const float*)d_in[7];
    const float* Wc   = (const float*)d_in[8];
    const float* bc   = (const float*)d_in[9];

    float* out      = (float*)d_out;
    float* out_pred = out;
    float* out_attn = out + (size_t)STEPS * BB * VV;

    init_kernel<<<192, 256>>>(emb, lf);

    for (int s = 0; s < STEPS; s++) {
        gates_gemm_kernel<<<dim3(128, 4), 128>>>(W_ih, W_hh);
        lstm_pointwise_kernel<<<64, 256>>>(b_ih, b_hh);
        attn_part_kernel<<<dim3(128, NP), 256>>>(lf);
        attn_combine_kernel<<<128, 128>>>(out_attn + (size_t)s * BB * TT);
        hid_gemm_kernel<<<128, 256>>>(Wp, bp);
        logits_gemm_kernel<<<dim3(313, 2), 128>>>(Wc);
        lsm_kernel<<<32, 512>>>(bc, emb, out_pred + (size_t)s * BB * VV);
    }
}